// round 3
// baseline (speedup 1.0000x reference)
#include <cuda_runtime.h>
#include <math.h>
#include <stdint.h>

#define H   1024
#define V   32000
#define B   32
#define T   64
#define G3H 3072
#define NMT 500                 // 32000/64 logits m-tiles
#define OUT_LOGP 65536000LL     // B*T*V

// ---------------- device scratch (no allocations allowed) ----------------
__device__ float g_h[2][H * B];        // hidden, transposed [k][b], double buffer
__device__ float g_C[6144 * B];        // GRU gate pre-activations [m][b]
__device__ int   g_tok[B];             // current token per batch
__device__ float g_pval[B][NMT];       // per-m-tile argmax partials
__device__ int   g_pidx[B][NMT];
__device__ float g_rowmax[B * T];      // max logit per (b,t) for log_softmax

// =====================================================================
// init: h0 = encoder_hidden[0] transposed; tok = SOS(0)
// =====================================================================
__global__ void init_k(const float* __restrict__ enc_h)
{
    int b = blockIdx.x, k = threadIdx.x;          // 32 x 1024
    g_h[0][k * B + b] = enc_h[b * H + k];
    if (b == 0 && k < B) g_tok[k] = 0;
}

// =====================================================================
// GRU gates GEMM: C[m][b] = sum_k W[m][k] * X[k][b]
//   blocks 0..47  : W_ih rows, X = relu(emb[tok[b]])
//   blocks 48..95 : W_hh rows, X = h_old
// tile 64m x 32b, K-tile 32; 256 threads; 4m x 2b per thread
// =====================================================================
__global__ void __launch_bounds__(256) gru_gemm(
    const float* __restrict__ Wih, const float* __restrict__ Whh,
    const float* __restrict__ emb, int t)
{
    const int m0 = blockIdx.x * 64;
    const bool ih = (m0 < G3H);
    const float* __restrict__ Wm = ih ? (Wih + (size_t)m0 * H)
                                      : (Whh + (size_t)(m0 - G3H) * H);
    const float* __restrict__ hb = g_h[t & 1];

    __shared__ float As[32][68];      // [kk][m]  (transposed, padded)
    __shared__ float Bs[32][36];      // [kk][b]
    __shared__ int   srow[B];

    const int tid = threadIdx.x;
    const int tm = tid & 15;          // 16 m-groups of 4
    const int tb = tid >> 4;          // 16 b-groups of 2
    const int am  = tid >> 2;         // A-loader: row 0..63
    const int ak0 = (tid & 3) * 8;    //           k offset 0,8,16,24
    const int lkk = tid >> 3;         // B-loader: k 0..31
    const int lb4 = (tid & 7) * 4;    //           b 0,4,..28

    if (tid < B) srow[tid] = g_tok[tid] * H;
    __syncthreads();

    float acc[2][4];
    #pragma unroll
    for (int j = 0; j < 2; j++)
        #pragma unroll
        for (int i = 0; i < 4; i++) acc[j][i] = 0.f;

    for (int kt = 0; kt < 32; kt++) {
        const int k0 = kt * 32;
        // A tile
        const float* wr = Wm + (size_t)am * H + k0 + ak0;
        float4 v0 = *(const float4*)wr;
        float4 v1 = *(const float4*)(wr + 4);
        As[ak0 + 0][am] = v0.x; As[ak0 + 1][am] = v0.y;
        As[ak0 + 2][am] = v0.z; As[ak0 + 3][am] = v0.w;
        As[ak0 + 4][am] = v1.x; As[ak0 + 5][am] = v1.y;
        As[ak0 + 6][am] = v1.z; As[ak0 + 7][am] = v1.w;
        // B tile
        if (ih) {
            #pragma unroll
            for (int j = 0; j < 4; j++)
                Bs[lkk][lb4 + j] = fmaxf(emb[(size_t)srow[lb4 + j] + k0 + lkk], 0.f);
        } else {
            float4 hv = *(const float4*)&hb[(k0 + lkk) * B + lb4];
            *(float4*)&Bs[lkk][lb4] = hv;
        }
        __syncthreads();

        #pragma unroll
        for (int kk = 0; kk < 32; kk++) {
            float4 a = *(const float4*)&As[kk][4 * tm];
            float2 bv = *(const float2*)&Bs[kk][2 * tb];
            acc[0][0] += a.x * bv.x; acc[0][1] += a.y * bv.x;
            acc[0][2] += a.z * bv.x; acc[0][3] += a.w * bv.x;
            acc[1][0] += a.x * bv.y; acc[1][1] += a.y * bv.y;
            acc[1][2] += a.z * bv.y; acc[1][3] += a.w * bv.y;
        }
        __syncthreads();
    }

    #pragma unroll
    for (int j = 0; j < 2; j++) {
        int b = 2 * tb + j;
        #pragma unroll
        for (int i = 0; i < 4; i++)
            g_C[(size_t)(m0 + 4 * tm + i) * B + b] = acc[j][i];
    }
}

// =====================================================================
// GRU cell: gates + biases -> h_new (writes buffer (t+1)&1)
// =====================================================================
__global__ void __launch_bounds__(256) gru_cell(
    const float* __restrict__ bih, const float* __restrict__ bhh, int t)
{
    int gid = blockIdx.x * 256 + threadIdx.x;      // 32768
    int b = gid >> 10;
    int j = gid & 1023;
    float gir = g_C[(size_t)(j)           * B + b];
    float giz = g_C[(size_t)(H + j)       * B + b];
    float gin = g_C[(size_t)(2 * H + j)   * B + b];
    float ghr = g_C[(size_t)(G3H + j)         * B + b];
    float ghz = g_C[(size_t)(G3H + H + j)     * B + b];
    float ghn = g_C[(size_t)(G3H + 2 * H + j) * B + b];
    float r = 1.f / (1.f + expf(-(gir + bih[j]       + ghr + bhh[j])));
    float z = 1.f / (1.f + expf(-(giz + bih[H + j]   + ghz + bhh[H + j])));
    float n = tanhf(gin + bih[2 * H + j] + r * (ghn + bhh[2 * H + j]));
    float hold = g_h[t & 1][j * B + b];
    g_h[(t + 1) & 1][j * B + b] = (1.f - z) * n + z * hold;
}

// =====================================================================
// Logits GEMM + bias + store + per-tile argmax partials
// reads h from buffer (t+1)&1
// =====================================================================
__global__ void __launch_bounds__(256) logits_gemm(
    const float* __restrict__ Wout, const float* __restrict__ bout,
    float* __restrict__ out, int t)
{
    const int mt = blockIdx.x;
    const int m0 = mt * 64;
    const float* __restrict__ Wm = Wout + (size_t)m0 * H;
    const float* __restrict__ hb = g_h[(t + 1) & 1];

    __shared__ float As[32][68];
    __shared__ float Bs[32][36];

    const int tid = threadIdx.x;
    const int tm = tid & 15;
    const int tb = tid >> 4;
    const int am  = tid >> 2;
    const int ak0 = (tid & 3) * 8;
    const int lkk = tid >> 3;
    const int lb4 = (tid & 7) * 4;

    float acc[2][4];
    #pragma unroll
    for (int j = 0; j < 2; j++)
        #pragma unroll
        for (int i = 0; i < 4; i++) acc[j][i] = 0.f;

    for (int kt = 0; kt < 32; kt++) {
        const int k0 = kt * 32;
        const float* wr = Wm + (size_t)am * H + k0 + ak0;
        float4 v0 = *(const float4*)wr;
        float4 v1 = *(const float4*)(wr + 4);
        As[ak0 + 0][am] = v0.x; As[ak0 + 1][am] = v0.y;
        As[ak0 + 2][am] = v0.z; As[ak0 + 3][am] = v0.w;
        As[ak0 + 4][am] = v1.x; As[ak0 + 5][am] = v1.y;
        As[ak0 + 6][am] = v1.z; As[ak0 + 7][am] = v1.w;
        float4 hv = *(const float4*)&hb[(k0 + lkk) * B + lb4];
        *(float4*)&Bs[lkk][lb4] = hv;
        __syncthreads();

        #pragma unroll
        for (int kk = 0; kk < 32; kk++) {
            float4 a = *(const float4*)&As[kk][4 * tm];
            float2 bv = *(const float2*)&Bs[kk][2 * tb];
            acc[0][0] += a.x * bv.x; acc[0][1] += a.y * bv.x;
            acc[0][2] += a.z * bv.x; acc[0][3] += a.w * bv.x;
            acc[1][0] += a.x * bv.y; acc[1][1] += a.y * bv.y;
            acc[1][2] += a.z * bv.y; acc[1][3] += a.w * bv.y;
        }
        __syncthreads();
    }

    float4 bias = *(const float4*)&bout[m0 + 4 * tm];
    #pragma unroll
    for (int j = 0; j < 2; j++) {
        int b = 2 * tb + j;
        float4 o;
        o.x = acc[j][0] + bias.x; o.y = acc[j][1] + bias.y;
        o.z = acc[j][2] + bias.z; o.w = acc[j][3] + bias.w;
        *(float4*)(out + ((size_t)b * T + t) * V + m0 + 4 * tm) = o;

        float bv = o.x; int bi = 0;
        if (o.y > bv) { bv = o.y; bi = 1; }
        if (o.z > bv) { bv = o.z; bi = 2; }
        if (o.w > bv) { bv = o.w; bi = 3; }
        int gidx = m0 + 4 * tm + bi;
        // reduce across 16 tm-lanes (same b within each 16-lane segment)
        #pragma unroll
        for (int off = 8; off > 0; off >>= 1) {
            float ov = __shfl_down_sync(0xffffffffu, bv, off, 16);
            int   oi = __shfl_down_sync(0xffffffffu, gidx, off, 16);
            if (ov > bv || (ov == bv && oi < gidx)) { bv = ov; gidx = oi; }
        }
        if (tm == 0) {
            g_pval[b][mt] = bv;
            g_pidx[b][mt] = gidx;
        }
    }
}

// =====================================================================
// finalize argmax across NMT partials -> next token + row max
// =====================================================================
__global__ void __launch_bounds__(1024) argmax_fin(int t)
{
    int b = threadIdx.x >> 5;
    int lane = threadIdx.x & 31;
    float v = -INFINITY;
    int idx = 0x7fffffff;
    for (int i = lane; i < NMT; i += 32) {
        float pv = g_pval[b][i];
        int   pi = g_pidx[b][i];
        if (pv > v || (pv == v && pi < idx)) { v = pv; idx = pi; }
    }
    #pragma unroll
    for (int off = 16; off > 0; off >>= 1) {
        float ov = __shfl_down_sync(0xffffffffu, v, off);
        int   oi = __shfl_down_sync(0xffffffffu, idx, off);
        if (ov > v || (ov == v && oi < idx)) { v = ov; idx = oi; }
    }
    if (lane == 0) {
        g_tok[b] = idx;
        g_rowmax[b * T + t] = v;
    }
}

// =====================================================================
// deferred log_softmax, in-place, one block per (b,t) row
// =====================================================================
__global__ void __launch_bounds__(256) lsm_k(float* __restrict__ out)
{
    __shared__ float red[256];
    int r = blockIdx.x;
    float* row = out + (size_t)r * V;
    float mx = g_rowmax[r];
    float s = 0.f;
    for (int i = threadIdx.x; i < V; i += 256)
        s += expf(row[i] - mx);
    red[threadIdx.x] = s;
    __syncthreads();
    for (int off = 128; off > 0; off >>= 1) {
        if (threadIdx.x < off) red[threadIdx.x] += red[threadIdx.x + off];
        __syncthreads();
    }
    float c = mx + logf(red[0]);
    for (int i = threadIdx.x; i < V; i += 256)
        row[i] = row[i] - c;
}

// =====================================================================
// copy final hidden (buffer 0 after 64 steps) to output tail
// =====================================================================
__global__ void copy_h(float* __restrict__ dst)
{
    int b = blockIdx.x, k = threadIdx.x;
    dst[b * H + k] = g_h[0][k * B + b];
}

// =====================================================================
extern "C" void kernel_launch(void* const* d_in, const int* in_sizes, int n_in,
                              void* d_out, int out_size)
{
    const float* enc_h = (const float*)d_in[1];
    const float* emb   = (const float*)d_in[2];
    const float* Wih   = (const float*)d_in[3];
    const float* Whh   = (const float*)d_in[4];
    const float* bih   = (const float*)d_in[5];
    const float* bhh   = (const float*)d_in[6];
    const float* Wout  = (const float*)d_in[7];
    const float* bout  = (const float*)d_in[8];
    float* out = (float*)d_out;

    init_k<<<B, H>>>(enc_h);
    for (int t = 0; t < T; t++) {
        gru_gemm<<<96, 256>>>(Wih, Whh, emb, t);
        gru_cell<<<128, 256>>>(bih, bhh, t);
        logits_gemm<<<NMT, 256>>>(Wout, bout, out, t);
        argmax_fin<<<1, 1024>>>(t);
    }
    lsm_k<<<B * T, 256>>>(out);
    if ((long long)out_size >= OUT_LOGP + (long long)B * H)
        copy_h<<<B, H>>>(out + OUT_LOGP);
}